// round 12
// baseline (speedup 1.0000x reference)
#include <cuda_runtime.h>
#include <cuda_bf16.h>

#define B_ 32
#define N_ 256
#define SEG_PER 4
#define SEG_BLK (N_ / SEG_PER)   // 64
#define TAIL_FR 8

// ---------------------------------------------------------------------------
// Single fused kernel. Grid (SEG_BLK + ceil(T/TAIL_FR), B_), 128 threads.
// Every block first runs is64-detect + a full 256-entry inclusive scan of its
// batch's durations row in smem (2 elements/thread, 7 Hillis-Steele steps).
//   blockIdx.x <  SEG_BLK -> segment-group block: 4 consecutive segments,
//                            each loads <=3 source rows once and stream-
//                            stores its d frames (float4 __stcs path).
//   blockIdx.x >= SEG_BLK -> tail block: 8 frames; mask + zero-fill of the
//                            contiguous inactive sub-range.
// int32/int64 detection: durations < 16, so if int64 every odd 32-bit word of
// the first 512 words is 0 (region in-bounds under both layouts).
// All barriers complete before any divergent exit.
// ---------------------------------------------------------------------------
__global__ __launch_bounds__(128) void main_kernel(
    const float4* __restrict__ start,
    const float4* __restrict__ mid,
    const float4* __restrict__ end,
    const void* __restrict__ dur_raw,
    const void* __restrict__ rc_raw,
    float4* __restrict__ out,
    float* __restrict__ mask_out,
    int T, int F4, int write_mask)
{
    const int b   = blockIdx.y;
    const int tid = threadIdx.x;

    __shared__ int shO[4];
    __shared__ int ps[128];
    __shared__ int cum_s[N_];

    // ---- detect int32 vs int64 (first 512 words, broadcast/L1-hot) ----
    const int4* d4 = (const int4*)dur_raw;
    int4 det = __ldg(d4 + tid);
    int odd = det.y | det.w;
    odd = __reduce_or_sync(0xffffffffu, odd);
    if ((tid & 31) == 0) shO[tid >> 5] = odd;
    __syncthreads();
    const int is64 = ((shO[0] | shO[1] | shO[2] | shO[3]) == 0) ? 1 : 0;

    // ---- load 2 durations per thread, full 256-entry inclusive scan ----
    int v0, v1;
    if (is64) {
        int4 w = __ldg(d4 + b * 128 + tid);   // longs 2*tid, 2*tid+1
        v0 = w.x; v1 = w.z;
    } else {
        int2 w = __ldg((const int2*)dur_raw + b * 128 + tid);
        v0 = w.x; v1 = w.y;
    }
    int pair = v0 + v1;
    ps[tid] = pair;
    __syncthreads();
#pragma unroll
    for (int off = 1; off < 128; off <<= 1) {
        int add = (tid >= off) ? ps[tid - off] : 0;
        __syncthreads();
        ps[tid] += add;
        __syncthreads();
    }
    const int incl = ps[tid];
    cum_s[2 * tid]     = incl - v1;
    cum_s[2 * tid + 1] = incl;
    __syncthreads();
    const int totalF = cum_s[N_ - 1];

    const int f0 = tid;

    if (blockIdx.x >= SEG_BLK) {
        // ---- tail / mask block: frames [tb, tb+TAIL_FR) ----
        const int tb = (blockIdx.x - SEG_BLK) * TAIL_FR;
        int total = totalF; if (total > T) total = T;
        if (write_mask && f0 < TAIL_FR && tb + f0 < T) {
            mask_out[b * T + tb + f0] = (tb + f0 < total) ? 1.0f : 0.0f;
        }
        if (tb + TAIL_FR <= total) return;    // fully active: nothing to zero
        const float4 z = make_float4(0.f, 0.f, 0.f, 0.f);
        const int ob = (b * T + tb) * F4 + f0;
#pragma unroll
        for (int k = 0; k < TAIL_FR; ++k) {
            const int t = tb + k;
            if (t >= total && t < T) __stcs(out + ob + k * F4, z);
        }
        return;
    }

    // ---- segment-group block: segments [g0, g0+SEG_PER) ----
    const int g0 = blockIdx.x * SEG_PER;
#pragma unroll
    for (int k = 0; k < SEG_PER; ++k) {
        const int idx = g0 + k;
        const int c1 = cum_s[idx];
        const int c0 = idx ? cum_s[idx - 1] : 0;
        const int d  = c1 - c0;
        if (d <= 0) continue;
        const int off = c0;
        if (off >= T) continue;

        const int cls = is64 ? (int)((const long long*)rc_raw)[b * N_ + idx]
                             : ((const int*)rc_raw)[b * N_ + idx];
        const bool lin = (cls == 1) && (d >= 4);

        const int rb = (b * N_ + idx) * F4 + f0;
        const bool need_s = lin || (d > 1);
        const bool need_e = lin || (d > 1);
        const bool need_m = lin || (d != 2);
        float4 s, m, e;
        if (need_s) s = __ldg(start + rb);
        if (need_m) m = __ldg(mid + rb);
        if (need_e) e = __ldg(end + rb);

        int pe = d; if (off + pe > T) pe = T - off;
        const int half = d >> 1;
        int den1 = half - 1;     if (den1 < 1) den1 = 1;
        int den2 = d - half - 1; if (den2 < 1) den2 = 1;
        const float inv1 = 1.0f / (float)den1;
        const float inv2 = 1.0f / (float)den2;

        float4* __restrict__ ob = out + (b * T + off) * F4 + f0;

        if (lin) {
#pragma unroll 4
            for (int p = 0; p < pe; ++p) {
                const bool fh = (p < half);
                const float w1 = fh ? (float)p * inv1
                                    : (float)(p - half) * inv2;
                const float w0 = 1.0f - w1;
                const float4 A  = fh ? s : m;
                const float4 Bv = fh ? m : e;
                float4 r;
                r.x = fmaf(A.x, w0, Bv.x * w1);
                r.y = fmaf(A.y, w0, Bv.y * w1);
                r.z = fmaf(A.z, w0, Bv.z * w1);
                r.w = fmaf(A.w, w0, Bv.w * w1);
                __stcs(ob + p * F4, r);
            }
        } else {
#pragma unroll 4
            for (int p = 0; p < pe; ++p) {
                float4 r = m;
                if (d > 1) {
                    if (p == 0)          r = s;
                    else if (p == d - 1) r = e;
                }
                __stcs(ob + p * F4, r);
            }
        }
    }
}

// ---------------------------------------------------------------------------
// Launch
// ---------------------------------------------------------------------------
extern "C" void kernel_launch(void* const* d_in, const int* in_sizes, int n_in,
                              void* d_out, int out_size) {
    const float* start = (const float*)d_in[0];
    const float* mid   = (const float*)d_in[1];
    const float* end   = (const float*)d_in[2];
    const void*  dur   = d_in[3];
    const void*  rc    = d_in[4];
    (void)n_in;

    const int BN = in_sizes[3];                 // B*N
    const int F  = in_sizes[0] / BN;            // 512
    const int F4 = F / 4;

    long long os = (long long)out_size;
    int T, write_mask;
    if (os % ((long long)B_ * (F + 1)) == 0) {
        T = (int)(os / ((long long)B_ * (F + 1)));
        write_mask = 1;
    } else {
        T = (int)(os / ((long long)B_ * F));
        write_mask = 0;
    }

    float* out_f  = (float*)d_out;
    float* mask_f = out_f + B_ * T * F;

    const int tail_blocks = (T + TAIL_FR - 1) / TAIL_FR;
    dim3 grid(SEG_BLK + tail_blocks, B_);
    main_kernel<<<grid, 128>>>(
        (const float4*)start, (const float4*)mid, (const float4*)end,
        dur, rc, (float4*)out_f, mask_f, T, F4, write_mask);
}